// round 2
// baseline (speedup 1.0000x reference)
#include <cuda_runtime.h>
#include <math.h>

#define NPIX   784
#define NPOS   676
#define NCH    8
#define NCLS   10
#define FLATK  5408
#define THREADS 128

typedef unsigned long long u64;

// Pre-broadcast dense weights: g_wdup[(c*676+p)*5 + j] = {w2j, w2j, w2j+1, w2j+1}
// where w_o = wdense[o*5408 + c*676 + p].  432 KB static device scratch.
__device__ float4 g_wdup[FLATK * 5];

__global__ void prep_wdense(const float* __restrict__ wd)
{
    int idx = blockIdx.x * blockDim.x + threadIdx.x;
    if (idx >= FLATK * 5) return;
    int cp = idx / 5, j = idx - cp * 5;
    float w0 = wd[(2 * j)     * FLATK + cp];
    float w1 = wd[(2 * j + 1) * FLATK + cp];
    g_wdup[idx] = make_float4(w0, w0, w1, w1);
}

__device__ __forceinline__ u64 packf2(float a, float b) {
    u64 r; asm("mov.b64 %0,{%1,%2};" : "=l"(r) : "f"(a), "f"(b)); return r;
}
__device__ __forceinline__ void unpackf2(u64 v, float& a, float& b) {
    asm("mov.b64 {%0,%1},%2;" : "=f"(a), "=f"(b) : "l"(v));
}
__device__ __forceinline__ u64 add2(u64 a, u64 b) {
    u64 r; asm("add.rn.f32x2 %0,%1,%2;" : "=l"(r) : "l"(a), "l"(b)); return r;
}
__device__ __forceinline__ u64 fma2(u64 a, u64 b, u64 c) {
    u64 r; asm("fma.rn.f32x2 %0,%1,%2,%3;" : "=l"(r) : "l"(a), "l"(b), "l"(c)); return r;
}

__global__ __launch_bounds__(THREADS)
void fused_afrnn_kernel(const float* __restrict__ x,
                        const float* __restrict__ wfuzzy,
                        float* __restrict__ out)
{
    __shared__ float4 sx4[NPIX];          // {im0,im1,im2,im3} per pixel, 12.5 KB
    __shared__ u64    sw2[NCH * 9];       // {w-1, w-1} packed fuzzy weights
    __shared__ float  red[4][4 * NCLS];
    __shared__ float  tot[4 * NCLS];

    const int tid  = threadIdx.x;
    const int img0 = blockIdx.x * 4;

    // ---- stage: transpose 4 images into interleaved smem ----
    {
        float* sxs = (float*)sx4;
        for (int idx = tid; idx < 4 * NPIX; idx += THREADS) {
            int im  = idx / NPIX;
            int pix = idx - im * NPIX;
            sxs[pix * 4 + im] = x[(size_t)img0 * NPIX + idx];
        }
        if (tid < NCH * 9) {
            float w = wfuzzy[tid] - 1.0f;   // fold the -1 of relu(max(...)-1)
            sw2[tid] = packf2(w, w);
        }
    }
    __syncthreads();

    // ---- packed accumulators: A = imgs{0,1}, B = imgs{2,3} ----
    u64 accA[NCLS], accB[NCLS];
    #pragma unroll
    for (int o = 0; o < NCLS; o++) { accA[o] = 0ull; accB[o] = 0ull; }

    for (int p = tid; p < NPOS; p += THREADS) {
        const int i    = p / 26;
        const int j    = p - i * 26;
        const int base = i * 28 + j;

        // 9-pixel window, all 4 images per LDS.128
        u64 pa[9], pb[9];
        #pragma unroll
        for (int r = 0; r < 3; r++)
            #pragma unroll
            for (int cc = 0; cc < 3; cc++) {
                float4 q = sx4[base + r * 28 + cc];
                pa[r * 3 + cc] = packf2(q.x, q.y);
                pb[r * 3 + cc] = packf2(q.z, q.w);
            }

        #pragma unroll
        for (int c = 0; c < NCH; c++) {
            const u64* w2 = &sw2[c * 9];

            // fz = relu(max_k(px + (w-1))) for 4 images (packed adds, scalar max)
            float m0, m1, m2, m3;
            {
                u64 t = add2(pa[0], w2[0]); unpackf2(t, m0, m1);
                u64 s = add2(pb[0], w2[0]); unpackf2(s, m2, m3);
            }
            #pragma unroll
            for (int k = 1; k < 9; k++) {
                float ax, ay, bx, by;
                u64 t = add2(pa[k], w2[k]); unpackf2(t, ax, ay);
                u64 s = add2(pb[k], w2[k]); unpackf2(s, bx, by);
                m0 = fmaxf(m0, ax); m1 = fmaxf(m1, ay);
                m2 = fmaxf(m2, bx); m3 = fmaxf(m3, by);
            }
            u64 fza = packf2(fmaxf(m0, 0.0f), fmaxf(m1, 0.0f));
            u64 fzb = packf2(fmaxf(m2, 0.0f), fmaxf(m3, 0.0f));

            // dense partials: 5 LDG.128, halves are pre-broadcast {w,w} pairs
            const ulonglong2* wv =
                (const ulonglong2*)(g_wdup + ((size_t)c * NPOS + p) * 5);
            #pragma unroll
            for (int jj = 0; jj < 5; jj++) {
                ulonglong2 q = wv[jj];
                accA[2 * jj]     = fma2(fza, q.x, accA[2 * jj]);
                accB[2 * jj]     = fma2(fzb, q.x, accB[2 * jj]);
                accA[2 * jj + 1] = fma2(fza, q.y, accA[2 * jj + 1]);
                accB[2 * jj + 1] = fma2(fzb, q.y, accB[2 * jj + 1]);
            }
        }
    }

    // ---- reduce partial logits across the block ----
    const int lane = tid & 31;
    const int wid  = tid >> 5;
    #pragma unroll
    for (int o = 0; o < NCLS; o++) {
        float v[4];
        unpackf2(accA[o], v[0], v[1]);
        unpackf2(accB[o], v[2], v[3]);
        #pragma unroll
        for (int im = 0; im < 4; im++) {
            float t = v[im];
            t += __shfl_down_sync(0xffffffffu, t, 16);
            t += __shfl_down_sync(0xffffffffu, t, 8);
            t += __shfl_down_sync(0xffffffffu, t, 4);
            t += __shfl_down_sync(0xffffffffu, t, 2);
            t += __shfl_down_sync(0xffffffffu, t, 1);
            if (lane == 0) red[wid][im * NCLS + o] = t;
        }
    }
    __syncthreads();

    if (tid < 4 * NCLS)
        tot[tid] = red[0][tid] + red[1][tid] + red[2][tid] + red[3][tid];
    __syncthreads();

    // ---- log_softmax (1 thread per image) ----
    if (tid < 4) {
        float l[NCLS];
        float mx = -1e30f;
        #pragma unroll
        for (int o = 0; o < NCLS; o++) {
            l[o] = tot[tid * NCLS + o];
            mx = fmaxf(mx, l[o]);
        }
        float s = 0.0f;
        #pragma unroll
        for (int o = 0; o < NCLS; o++) s += expf(l[o] - mx);
        const float lse = mx + logf(s);
        float* op = out + (size_t)(img0 + tid) * NCLS;
        #pragma unroll
        for (int o = 0; o < NCLS; o++) op[o] = l[o] - lse;
    }
}

extern "C" void kernel_launch(void* const* d_in, const int* in_sizes, int n_in,
                              void* d_out, int out_size)
{
    const float* x  = (const float*)d_in[0];   // (4096,1,28,28) fp32
    const float* wf = (const float*)d_in[1];   // (8,1,3,3)      fp32
    const float* wd = (const float*)d_in[2];   // (10,5408)      fp32
    float* out = (float*)d_out;                // (4096,10)      fp32

    const int nimg = in_sizes[0] / NPIX;       // 4096
    prep_wdense<<<(FLATK * 5 + 255) / 256, 256>>>(wd);
    fused_afrnn_kernel<<<nimg / 4, THREADS>>>(x, wf, out);
}

// round 3
// speedup vs baseline: 1.2811x; 1.2811x over previous
#include <cuda_runtime.h>
#include <math.h>

#define NPIX   784
#define NPOS   676
#define NCH    8
#define NCLS   10
#define FLATK  5408
#define THREADS 128

typedef unsigned long long u64;

// Transposed dense weights: g_wt[(c*676+p)*3 + j] = {w_{4j},w_{4j+1},w_{4j+2},w_{4j+3}}
// where w_o = wdense[o*5408 + (c*676+p)], padded to 12 floats/row. 260 KB.
__device__ float4 g_wt[FLATK * 3];

__global__ void prep_wdense(const float* __restrict__ wd)
{
    int idx = blockIdx.x * blockDim.x + threadIdx.x;
    if (idx >= FLATK * 3) return;
    int cp = idx / 3, j = idx - cp * 3;
    float v[4];
    #pragma unroll
    for (int k = 0; k < 4; k++) {
        int o = j * 4 + k;
        v[k] = (o < NCLS) ? wd[o * FLATK + cp] : 0.0f;
    }
    g_wt[idx] = make_float4(v[0], v[1], v[2], v[3]);
}

__device__ __forceinline__ u64 packf2(float a, float b) {
    u64 r; asm("mov.b64 %0,{%1,%2};" : "=l"(r) : "f"(a), "f"(b)); return r;
}
__device__ __forceinline__ void unpackf2(u64 v, float& a, float& b) {
    asm("mov.b64 {%0,%1},%2;" : "=f"(a), "=f"(b) : "l"(v));
}
__device__ __forceinline__ u64 fma2(u64 a, u64 b, u64 c) {
    u64 r; asm("fma.rn.f32x2 %0,%1,%2,%3;" : "=l"(r) : "l"(a), "l"(b), "l"(c)); return r;
}

__global__ __launch_bounds__(THREADS, 4)
void fused_afrnn_kernel(const float* __restrict__ x,
                        const float* __restrict__ wfuzzy,
                        float* __restrict__ out)
{
    __shared__ float4 sx4[NPIX];        // {im0..im3} per pixel, 12.5 KB
    __shared__ float4 swf[NCH * 3];     // (w-1) padded to 12/row
    __shared__ float  red[4][4 * NCLS];
    __shared__ float  tot[4 * NCLS];

    const int tid  = threadIdx.x;
    const int img0 = blockIdx.x * 4;

    // ---- stage: transpose 4 images into interleaved smem ----
    {
        float* sxs = (float*)sx4;
        for (int idx = tid; idx < 4 * NPIX; idx += THREADS) {
            int im  = idx / NPIX;
            int pix = idx - im * NPIX;
            sxs[pix * 4 + im] = x[(size_t)img0 * NPIX + idx];
        }
        if (tid < NCH * 3) {
            int c = tid / 3, j = tid - c * 3;
            float v[4];
            #pragma unroll
            for (int k = 0; k < 4; k++) {
                int o = j * 4 + k;
                v[k] = (o < 9) ? (wfuzzy[c * 9 + o] - 1.0f) : -1e30f;
            }
            swf[tid] = make_float4(v[0], v[1], v[2], v[3]);
        }
    }
    __syncthreads();

    // ---- packed accumulators: acc[im][j] = {logit_2j, logit_2j+1} ----
    u64 acc[4][5];
    #pragma unroll
    for (int im = 0; im < 4; im++)
        #pragma unroll
        for (int j = 0; j < 5; j++) acc[im][j] = 0ull;

    for (int p = tid; p < NPOS; p += THREADS) {
        const int i    = p / 26;
        const int j    = p - i * 26;
        const int base = i * 28 + j;

        // 9 pixels x 4 images via LDS.128
        float4 q[9];
        #pragma unroll
        for (int r = 0; r < 3; r++)
            #pragma unroll
            for (int cc = 0; cc < 3; cc++)
                q[r * 3 + cc] = sx4[base + r * 28 + cc];

        #pragma unroll
        for (int c = 0; c < NCH; c++) {
            // fuzzy weights (w-1), 3 LDS.128
            const float4 wA = swf[c * 3 + 0];
            const float4 wB = swf[c * 3 + 1];
            const float4 wC = swf[c * 3 + 2];
            const float w[9] = { wA.x, wA.y, wA.z, wA.w,
                                 wB.x, wB.y, wB.z, wB.w, wC.x };

            // fz = relu(max_k(px + (w-1))) per image
            float m0 = q[0].x + w[0], m1 = q[0].y + w[0];
            float m2 = q[0].z + w[0], m3 = q[0].w + w[0];
            #pragma unroll
            for (int k = 1; k < 9; k++) {
                m0 = fmaxf(m0, q[k].x + w[k]);
                m1 = fmaxf(m1, q[k].y + w[k]);
                m2 = fmaxf(m2, q[k].z + w[k]);
                m3 = fmaxf(m3, q[k].w + w[k]);
            }
            const u64 fz0 = packf2(fmaxf(m0, 0.0f), fmaxf(m0, 0.0f));
            const u64 fz1 = packf2(fmaxf(m1, 0.0f), fmaxf(m1, 0.0f));
            const u64 fz2 = packf2(fmaxf(m2, 0.0f), fmaxf(m2, 0.0f));
            const u64 fz3 = packf2(fmaxf(m3, 0.0f), fmaxf(m3, 0.0f));

            // dense: weight pairs {w_2j, w_2j+1} straight from transposed rows
            const char* row = (const char*)(g_wt + ((size_t)c * NPOS + p) * 3);
            const ulonglong2 t0 = *(const ulonglong2*)(row);      // w0w1, w2w3
            const ulonglong2 t1 = *(const ulonglong2*)(row + 16); // w4w5, w6w7
            const u64        t2 = *(const u64*)(row + 32);        // w8w9
            const u64 wp[5] = { t0.x, t0.y, t1.x, t1.y, t2 };

            #pragma unroll
            for (int jj = 0; jj < 5; jj++) {
                acc[0][jj] = fma2(fz0, wp[jj], acc[0][jj]);
                acc[1][jj] = fma2(fz1, wp[jj], acc[1][jj]);
                acc[2][jj] = fma2(fz2, wp[jj], acc[2][jj]);
                acc[3][jj] = fma2(fz3, wp[jj], acc[3][jj]);
            }
        }
    }

    // ---- reduce partial logits across the block ----
    const int lane = tid & 31;
    const int wid  = tid >> 5;
    #pragma unroll
    for (int im = 0; im < 4; im++) {
        #pragma unroll
        for (int jj = 0; jj < 5; jj++) {
            float a, b;
            unpackf2(acc[im][jj], a, b);
            #pragma unroll
            for (int h = 0; h < 2; h++) {
                float t = h ? b : a;
                t += __shfl_down_sync(0xffffffffu, t, 16);
                t += __shfl_down_sync(0xffffffffu, t, 8);
                t += __shfl_down_sync(0xffffffffu, t, 4);
                t += __shfl_down_sync(0xffffffffu, t, 2);
                t += __shfl_down_sync(0xffffffffu, t, 1);
                if (lane == 0) red[wid][im * NCLS + 2 * jj + h] = t;
            }
        }
    }
    __syncthreads();

    if (tid < 4 * NCLS)
        tot[tid] = red[0][tid] + red[1][tid] + red[2][tid] + red[3][tid];
    __syncthreads();

    // ---- log_softmax (1 thread per image) ----
    if (tid < 4) {
        float l[NCLS];
        float mx = -1e30f;
        #pragma unroll
        for (int o = 0; o < NCLS; o++) {
            l[o] = tot[tid * NCLS + o];
            mx = fmaxf(mx, l[o]);
        }
        float s = 0.0f;
        #pragma unroll
        for (int o = 0; o < NCLS; o++) s += expf(l[o] - mx);
        const float lse = mx + logf(s);
        float* op = out + (size_t)(img0 + tid) * NCLS;
        #pragma unroll
        for (int o = 0; o < NCLS; o++) op[o] = l[o] - lse;
    }
}

extern "C" void kernel_launch(void* const* d_in, const int* in_sizes, int n_in,
                              void* d_out, int out_size)
{
    const float* x  = (const float*)d_in[0];   // (4096,1,28,28) fp32
    const float* wf = (const float*)d_in[1];   // (8,1,3,3)      fp32
    const float* wd = (const float*)d_in[2];   // (10,5408)      fp32
    float* out = (float*)d_out;                // (4096,10)      fp32

    const int nimg = in_sizes[0] / NPIX;       // 4096
    prep_wdense<<<(FLATK * 3 + 255) / 256, 256>>>(wd);
    fused_afrnn_kernel<<<nimg / 4, THREADS>>>(x, wf, out);
}

// round 4
// speedup vs baseline: 1.4411x; 1.1249x over previous
#include <cuda_runtime.h>
#include <math.h>

#define NPIX   784
#define NPOS   676
#define NCH    8
#define NCLS   10
#define FLATK  5408
#define THREADS 128
#define IMGB   2

// Transposed dense weights: g_wt[cp] = row of 12 floats {w_0..w_9,0,0},
// w_o = wdense[o*5408 + cp].  260 KB static scratch.
__device__ float4 g_wt[FLATK * 3];

__global__ void prep_wdense(const float* __restrict__ wd)
{
    int idx = blockIdx.x * blockDim.x + threadIdx.x;
    if (idx >= FLATK * 3) return;
    int cp = idx / 3, j = idx - cp * 3;
    float v[4];
    #pragma unroll
    for (int k = 0; k < 4; k++) {
        int o = j * 4 + k;
        v[k] = (o < NCLS) ? wd[o * FLATK + cp] : 0.0f;
    }
    g_wt[idx] = make_float4(v[0], v[1], v[2], v[3]);
}

__global__ __launch_bounds__(THREADS, 5)
void fused_afrnn_kernel(const float* __restrict__ x,
                        const float* __restrict__ wfuzzy,
                        float* __restrict__ out)
{
    __shared__ float2 sx2[NPIX];        // {im0, im1} per pixel, 6.3 KB
    __shared__ float4 swf[NCH * 3];     // (w-1) padded to 12/row
    __shared__ float  red[4][IMGB * NCLS];
    __shared__ float  tot[IMGB * NCLS];

    const int tid  = threadIdx.x;
    const int img0 = blockIdx.x * IMGB;

    // ---- stage: interleave 2 images; coalesced across the image dim ----
    {
        const float* x0 = x + (size_t)img0 * NPIX;
        for (int pix = tid; pix < NPIX; pix += THREADS)
            sx2[pix] = make_float2(x0[pix], x0[pix + NPIX]);
        if (tid < NCH * 3) {
            int c = tid / 3, j = tid - c * 3;
            float v[4];
            #pragma unroll
            for (int k = 0; k < 4; k++) {
                int o = j * 4 + k;
                v[k] = (o < 9) ? (wfuzzy[c * 9 + o] - 1.0f) : 0.0f;
            }
            swf[tid] = make_float4(v[0], v[1], v[2], v[3]);
        }
    }
    __syncthreads();

    float acc0[NCLS], acc1[NCLS];
    #pragma unroll
    for (int o = 0; o < NCLS; o++) { acc0[o] = 0.0f; acc1[o] = 0.0f; }

    for (int p = tid; p < NPOS; p += THREADS) {
        const int i    = p / 26;
        const int j    = p - i * 26;
        const int base = i * 28 + j;

        // 3x3 window for both images: 9 LDS.64
        float2 q[9];
        #pragma unroll
        for (int r = 0; r < 3; r++)
            #pragma unroll
            for (int cc = 0; cc < 3; cc++)
                q[r * 3 + cc] = sx2[base + r * 28 + cc];

        #pragma unroll
        for (int c = 0; c < NCH; c++) {
            // fuzzy weights (w-1): 3 broadcast LDS.128
            const float4 wA = swf[c * 3 + 0];
            const float4 wB = swf[c * 3 + 1];
            const float4 wC = swf[c * 3 + 2];
            const float w[9] = { wA.x, wA.y, wA.z, wA.w,
                                 wB.x, wB.y, wB.z, wB.w, wC.x };

            // fz = relu(max_k(px + (w-1)))
            float m0 = q[0].x + w[0];
            float m1 = q[0].y + w[0];
            #pragma unroll
            for (int k = 1; k < 9; k++) {
                m0 = fmaxf(m0, q[k].x + w[k]);
                m1 = fmaxf(m1, q[k].y + w[k]);
            }
            const float fz0 = fmaxf(m0, 0.0f);
            const float fz1 = fmaxf(m1, 0.0f);

            // dense: 10 weights via 2x LDG.128 + 1x LDG.64 (transposed rows)
            const char* row = (const char*)(g_wt + ((size_t)c * NPOS + p) * 3);
            const float4 t0 = __ldg((const float4*)row);
            const float4 t1 = __ldg((const float4*)(row + 16));
            const float2 t2 = __ldg((const float2*)(row + 32));
            const float wv[NCLS] = { t0.x, t0.y, t0.z, t0.w,
                                     t1.x, t1.y, t1.z, t1.w,
                                     t2.x, t2.y };
            #pragma unroll
            for (int o = 0; o < NCLS; o++) {
                acc0[o] = fmaf(fz0, wv[o], acc0[o]);
                acc1[o] = fmaf(fz1, wv[o], acc1[o]);
            }
        }
    }

    // ---- reduce partial logits across the block ----
    const int lane = tid & 31;
    const int wid  = tid >> 5;
    #pragma unroll
    for (int o = 0; o < NCLS; o++) {
        #pragma unroll
        for (int im = 0; im < IMGB; im++) {
            float t = im ? acc1[o] : acc0[o];
            t += __shfl_down_sync(0xffffffffu, t, 16);
            t += __shfl_down_sync(0xffffffffu, t, 8);
            t += __shfl_down_sync(0xffffffffu, t, 4);
            t += __shfl_down_sync(0xffffffffu, t, 2);
            t += __shfl_down_sync(0xffffffffu, t, 1);
            if (lane == 0) red[wid][im * NCLS + o] = t;
        }
    }
    __syncthreads();

    if (tid < IMGB * NCLS)
        tot[tid] = red[0][tid] + red[1][tid] + red[2][tid] + red[3][tid];
    __syncthreads();

    // ---- log_softmax (1 thread per image) ----
    if (tid < IMGB) {
        float l[NCLS];
        float mx = -1e30f;
        #pragma unroll
        for (int o = 0; o < NCLS; o++) {
            l[o] = tot[tid * NCLS + o];
            mx = fmaxf(mx, l[o]);
        }
        float s = 0.0f;
        #pragma unroll
        for (int o = 0; o < NCLS; o++) s += expf(l[o] - mx);
        const float lse = mx + logf(s);
        float* op = out + (size_t)(img0 + tid) * NCLS;
        #pragma unroll
        for (int o = 0; o < NCLS; o++) op[o] = l[o] - lse;
    }
}

extern "C" void kernel_launch(void* const* d_in, const int* in_sizes, int n_in,
                              void* d_out, int out_size)
{
    const float* x  = (const float*)d_in[0];   // (4096,1,28,28) fp32
    const float* wf = (const float*)d_in[1];   // (8,1,3,3)      fp32
    const float* wd = (const float*)d_in[2];   // (10,5408)      fp32
    float* out = (float*)d_out;                // (4096,10)      fp32

    const int nimg = in_sizes[0] / NPIX;       // 4096
    prep_wdense<<<(FLATK * 3 + 255) / 256, 256>>>(wd);
    fused_afrnn_kernel<<<nimg / IMGB, THREADS>>>(x, wf, out);
}

// round 5
// speedup vs baseline: 1.8676x; 1.2960x over previous
#include <cuda_runtime.h>
#include <math.h>

#define NPIX   784
#define NPOS   676
#define NCH    8
#define NCLS   10
#define FLATK  5408
#define THREADS 128
#define IMGB   4

// Transposed dense weights: g_wt[cp*3 + j] = {w_{4j}..w_{4j+3}},
// w_o = wdense[o*5408 + cp], rows padded to 12 floats. 260 KB static scratch.
__device__ float4 g_wt[FLATK * 3];

__global__ void prep_wdense(const float* __restrict__ wd)
{
    int idx = blockIdx.x * blockDim.x + threadIdx.x;
    if (idx >= FLATK * 3) return;
    int cp = idx / 3, j = idx - cp * 3;
    float v[4];
    #pragma unroll
    for (int k = 0; k < 4; k++) {
        int o = j * 4 + k;
        v[k] = (o < NCLS) ? wd[o * FLATK + cp] : 0.0f;
    }
    g_wt[idx] = make_float4(v[0], v[1], v[2], v[3]);
}

__global__ __launch_bounds__(THREADS, 4)
void fused_afrnn_kernel(const float* __restrict__ x,
                        const float* __restrict__ wfuzzy,
                        float* __restrict__ out)
{
    __shared__ float4 sx4[NPIX];        // {im0..im3} per pixel, 12.5 KB
    __shared__ float4 swf[NCH * 3];     // (w-1) padded to 12/row
    __shared__ float  red[4][IMGB * NCLS];
    __shared__ float  tot[IMGB * NCLS];

    const int tid  = threadIdx.x;
    const int img0 = blockIdx.x * IMGB;

    // ---- stage: transpose 4 images into interleaved smem ----
    {
        float* sxs = (float*)sx4;
        const float* x0 = x + (size_t)img0 * NPIX;
        for (int idx = tid; idx < IMGB * NPIX; idx += THREADS) {
            int im  = idx / NPIX;
            int pix = idx - im * NPIX;
            sxs[pix * 4 + im] = x0[idx];
        }
        if (tid < NCH * 3) {
            int c = tid / 3, j = tid - c * 3;
            float v[4];
            #pragma unroll
            for (int k = 0; k < 4; k++) {
                int o = j * 4 + k;
                v[k] = (o < 9) ? (wfuzzy[c * 9 + o] - 1.0f) : 0.0f;
            }
            swf[tid] = make_float4(v[0], v[1], v[2], v[3]);
        }
    }
    __syncthreads();

    float acc[IMGB][NCLS];
    #pragma unroll
    for (int im = 0; im < IMGB; im++)
        #pragma unroll
        for (int o = 0; o < NCLS; o++) acc[im][o] = 0.0f;

    for (int p = tid; p < NPOS; p += THREADS) {
        const int i    = p / 26;
        const int j    = p - i * 26;
        const int base = i * 28 + j;

        // 3x3 window x 4 images: 9 LDS.128, conflict-free
        float4 q[9];
        #pragma unroll
        for (int r = 0; r < 3; r++)
            #pragma unroll
            for (int cc = 0; cc < 3; cc++)
                q[r * 3 + cc] = sx4[base + r * 28 + cc];

        #pragma unroll
        for (int c = 0; c < NCH; c++) {
            // fuzzy weights (w-1): 3 broadcast LDS.128
            const float4 wA = swf[c * 3 + 0];
            const float4 wB = swf[c * 3 + 1];
            const float4 wC = swf[c * 3 + 2];
            const float w[9] = { wA.x, wA.y, wA.z, wA.w,
                                 wB.x, wB.y, wB.z, wB.w, wC.x };

            // fz = relu(max_k(px + (w-1))), tree-shaped max per image
            float fz[IMGB];
            #pragma unroll
            for (int im = 0; im < IMGB; im++) {
                const float* qq = (const float*)&q[0] + im; // stride-4 view
                float a0 = qq[0*4]  + w[0];
                float a1 = qq[1*4]  + w[1];
                float a2 = qq[2*4]  + w[2];
                float a3 = qq[3*4]  + w[3];
                float a4 = qq[4*4]  + w[4];
                float a5 = qq[5*4]  + w[5];
                float a6 = qq[6*4]  + w[6];
                float a7 = qq[7*4]  + w[7];
                float a8 = qq[8*4]  + w[8];
                float b0 = fmaxf(a0, a1);
                float b1 = fmaxf(a2, a3);
                float b2 = fmaxf(a4, a5);
                float b3 = fmaxf(a6, a7);
                float c0 = fmaxf(b0, b1);
                float c1 = fmaxf(b2, b3);
                float m  = fmaxf(fmaxf(c0, c1), a8);
                fz[im] = fmaxf(m, 0.0f);
            }

            // dense: 10 weights via 2x LDG.128 + 1x LDG.64 (transposed rows)
            const char* row = (const char*)(g_wt + ((size_t)c * NPOS + p) * 3);
            const float4 t0 = __ldg((const float4*)row);
            const float4 t1 = __ldg((const float4*)(row + 16));
            const float2 t2 = __ldg((const float2*)(row + 32));
            const float wv[NCLS] = { t0.x, t0.y, t0.z, t0.w,
                                     t1.x, t1.y, t1.z, t1.w,
                                     t2.x, t2.y };
            #pragma unroll
            for (int o = 0; o < NCLS; o++) {
                #pragma unroll
                for (int im = 0; im < IMGB; im++)
                    acc[im][o] = fmaf(fz[im], wv[o], acc[im][o]);
            }
        }
    }

    // ---- reduce partial logits across the block ----
    const int lane = tid & 31;
    const int wid  = tid >> 5;
    #pragma unroll
    for (int im = 0; im < IMGB; im++) {
        #pragma unroll
        for (int o = 0; o < NCLS; o++) {
            float t = acc[im][o];
            t += __shfl_down_sync(0xffffffffu, t, 16);
            t += __shfl_down_sync(0xffffffffu, t, 8);
            t += __shfl_down_sync(0xffffffffu, t, 4);
            t += __shfl_down_sync(0xffffffffu, t, 2);
            t += __shfl_down_sync(0xffffffffu, t, 1);
            if (lane == 0) red[wid][im * NCLS + o] = t;
        }
    }
    __syncthreads();

    if (tid < IMGB * NCLS)
        tot[tid] = red[0][tid] + red[1][tid] + red[2][tid] + red[3][tid];
    __syncthreads();

    // ---- log_softmax (1 thread per image) ----
    if (tid < IMGB) {
        float l[NCLS];
        float mx = -1e30f;
        #pragma unroll
        for (int o = 0; o < NCLS; o++) {
            l[o] = tot[tid * NCLS + o];
            mx = fmaxf(mx, l[o]);
        }
        float s = 0.0f;
        #pragma unroll
        for (int o = 0; o < NCLS; o++) s += expf(l[o] - mx);
        const float lse = mx + logf(s);
        float* op = out + (size_t)(img0 + tid) * NCLS;
        #pragma unroll
        for (int o = 0; o < NCLS; o++) op[o] = l[o] - lse;
    }
}

extern "C" void kernel_launch(void* const* d_in, const int* in_sizes, int n_in,
                              void* d_out, int out_size)
{
    const float* x  = (const float*)d_in[0];   // (4096,1,28,28) fp32
    const float* wf = (const float*)d_in[1];   // (8,1,3,3)      fp32
    const float* wd = (const float*)d_in[2];   // (10,5408)      fp32
    float* out = (float*)d_out;                // (4096,10)      fp32

    const int nimg = in_sizes[0] / NPIX;       // 4096
    prep_wdense<<<(FLATK * 3 + 255) / 256, 256>>>(wd);
    fused_afrnn_kernel<<<nimg / IMGB, THREADS>>>(x, wf, out);
}